// round 2
// baseline (speedup 1.0000x reference)
#include <cuda_runtime.h>
#include <stdint.h>

// ---- SOM constants (match reference) ----
#define NODES 4096
#define FEATS 256
#define BATCH 1024
#define SIGMA_F 70.4f        // max(M,N) * 1.1
#define TOTAL_ITER_F 100000.0f

typedef unsigned long long u64;

// ---- device scratch (no allocations allowed) ----
__device__ u64   g_best[BATCH];
__device__ int   g_bmu[BATCH];
__device__ float g_w2[NODES];
__device__ float g_params[3];   // [0]=lr, [1]=1/(2 r^2), [2]=r^2

// ---- packed f32x2 helpers (FFMA2) ----
__device__ __forceinline__ void ffma2(u64 &c, u64 a, u64 b) {
    asm("fma.rn.f32x2 %0, %1, %2, %0;" : "+l"(c) : "l"(a), "l"(b));
}
__device__ __forceinline__ u64 dup2(float a) {
    u64 d; asm("mov.b64 %0, {%1, %1};" : "=l"(d) : "f"(a)); return d;
}
__device__ __forceinline__ float2 unpk(u64 d) {
    float2 r; asm("mov.b64 {%0, %1}, %2;" : "=f"(r.x), "=f"(r.y) : "l"(d));
    return r;
}

// ============================================================
// K0: reset argmin keys + compute decayed lr / radius params
// ============================================================
__global__ void k_init(const int* __restrict__ iter) {
    int t = blockIdx.x * blockDim.x + threadIdx.x;
    if (t < BATCH) g_best[t] = 0xFFFFFFFFFFFFFFFFull;
    if (t == 0) {
        float lambda_g = TOTAL_ITER_F / SIGMA_F;
        float decay    = expf(-(float)iter[0] / lambda_g);
        float radius   = SIGMA_F * decay + 1e-6f;
        g_params[0] = 0.5f * decay;
        g_params[1] = 1.0f / (2.0f * radius * radius);
        g_params[2] = radius * radius;
    }
}

// ============================================================
// K1: w2[n] = sum_d w[n,d]^2   (one warp per node)
// ============================================================
__global__ void k_w2(const float* __restrict__ w) {
    int warp = threadIdx.x >> 5, lane = threadIdx.x & 31;
    int n = blockIdx.x * 8 + warp;
    const float4* row = (const float4*)(w + (size_t)n * FEATS);
    float s = 0.0f;
    #pragma unroll
    for (int i = 0; i < 2; i++) {
        float4 v = row[lane + 32 * i];
        s += v.x * v.x + v.y * v.y + v.z * v.z + v.w * v.w;
    }
    #pragma unroll
    for (int o = 16; o; o >>= 1) s += __shfl_xor_sync(0xFFFFFFFFu, s, o);
    if (lane == 0) g_w2[n] = s;
}

// ============================================================
// K2: distance GEMM fused with argmin, FFMA2 packed math.
// Block tile 128 samples x 128 nodes, 256 threads, 8x8/thread.
// ws staged k-major so node pairs are contiguous (LDS.128 -> f32x2 pairs).
// dist = w2[n] - 2*x.w  (x^2 row-constant, argmin-invariant).
// ============================================================
#define XS_STRIDE 36
#define WT_STRIDE 132
__global__ void __launch_bounds__(256, 2) k_bmu(const float* __restrict__ x,
                                                const float* __restrict__ w) {
    __shared__ float xs[128][XS_STRIDE];    // sample-major [m][k]
    __shared__ float ws_t[32][WT_STRIDE];   // k-major      [k][n]
    int tid = threadIdx.x;
    int n0 = blockIdx.x * 128;
    int m0 = blockIdx.y * 128;
    int ty = tid >> 4, tx = tid & 15;       // ty: 8 samples, tx: 8 nodes

    u64 acc[8][4];
    #pragma unroll
    for (int i = 0; i < 8; i++)
        #pragma unroll
        for (int p = 0; p < 4; p++) acc[i][p] = 0ull;   // {+0.f,+0.f}

    int t8 = tid >> 3;            // 0..31
    int c4 = (tid & 7) * 4;       // 0..28

    for (int k0 = 0; k0 < FEATS; k0 += 32) {
        __syncthreads();
        #pragma unroll
        for (int q = 0; q < 4; q++) {
            int row = q * 32 + t8;
            float4 vx = *(const float4*)&x[(size_t)(m0 + row) * FEATS + k0 + c4];
            *(float4*)&xs[row][c4] = vx;
            float4 vw = *(const float4*)&w[(size_t)(n0 + row) * FEATS + k0 + c4];
            ws_t[c4 + 0][row] = vw.x;
            ws_t[c4 + 1][row] = vw.y;
            ws_t[c4 + 2][row] = vw.z;
            ws_t[c4 + 3][row] = vw.w;
        }
        __syncthreads();

        #pragma unroll
        for (int k = 0; k < 32; k++) {
            u64 ad[8];
            #pragma unroll
            for (int i = 0; i < 8; i++) ad[i] = dup2(xs[ty * 8 + i][k]);
            const ulonglong2* bp = (const ulonglong2*)&ws_t[k][tx * 8];
            ulonglong2 bA = bp[0], bB = bp[1];
            #pragma unroll
            for (int i = 0; i < 8; i++) {
                ffma2(acc[i][0], ad[i], bA.x);
                ffma2(acc[i][1], ad[i], bA.y);
                ffma2(acc[i][2], ad[i], bB.x);
                ffma2(acc[i][3], ad[i], bB.y);
            }
        }
    }

    // epilogue: per-sample argmin over this block's 128 nodes
    float w2v[8];
    #pragma unroll
    for (int j = 0; j < 8; j++) w2v[j] = g_w2[n0 + tx * 8 + j];

    #pragma unroll
    for (int i = 0; i < 8; i++) {
        float best = __int_as_float(0x7F800000);
        int bestn = 0;
        #pragma unroll
        for (int p = 0; p < 4; p++) {
            float2 v = unpk(acc[i][p]);
            int nl = n0 + tx * 8 + 2 * p;
            float d0 = w2v[2 * p] - 2.0f * v.x;
            float d1 = w2v[2 * p + 1] - 2.0f * v.y;
            if (d0 < best) { best = d0; bestn = nl; }
            if (d1 < best) { best = d1; bestn = nl + 1; }
        }
        #pragma unroll
        for (int o = 8; o; o >>= 1) {
            float od = __shfl_xor_sync(0xFFFFFFFFu, best, o);
            int   on = __shfl_xor_sync(0xFFFFFFFFu, bestn, o);
            if (od < best || (od == best && on < bestn)) { best = od; bestn = on; }
        }
        if (tx == 0) {
            unsigned u = __float_as_uint(best);
            u = (u & 0x80000000u) ? ~u : (u | 0x80000000u);
            u64 key = ((u64)u << 32) | (unsigned)bestn;
            atomicMin(&g_best[m0 + ty * 8 + i], key);
        }
    }
}

// ============================================================
// K3: unpack bmu indices; emit them (as float) after the map if room
// ============================================================
__global__ void k_finalize(float* __restrict__ out, int out_size) {
    int b = blockIdx.x * blockDim.x + threadIdx.x;
    if (b < BATCH) {
        int n = (int)(unsigned)(g_best[b] & 0xFFFFFFFFull);
        g_bmu[b] = n;
        if (out_size >= NODES * FEATS + BATCH)
            out[NODES * FEATS + b] = (float)n;
    }
}

// ============================================================
// K4: update GEMM C[n,d] = sum_b L[n,b] * X[b,d], FFMA2 packed.
// Block tile 64 nodes x 128 feats, 256 threads, 4x8/thread.
// L tile (lr_op) generated per 32-b chunk: b=lane, n=warp+8q;
// column sums via warp shuffle reduce (lane 0 accumulates).
// ============================================================
#define LT_STRIDE 65
#define XU_STRIDE 132
__global__ void __launch_bounds__(256) k_update(const float* __restrict__ x,
                                                const float* __restrict__ w,
                                                float* __restrict__ out) {
    __shared__ float Lt[32][LT_STRIDE];    // [b][n] lr_op tile
    __shared__ float xu[32][XU_STRIDE];    // [b][d] x tile
    __shared__ float s_sm[64];             // column sums of L

    int tid = threadIdx.x;
    int bx = blockIdx.x;
    int n0 = (bx & 63) * 64;
    int d0 = (bx >> 6) * 128;
    int ty = tid >> 4, tx = tid & 15;      // ty: 4 nodes, tx: 8 feats
    int warp = tid >> 5, lane = tid & 31;

    float lr = g_params[0], inv2r2 = g_params[1], r2 = g_params[2];

    u64 acc[4][4];
    #pragma unroll
    for (int i = 0; i < 4; i++)
        #pragma unroll
        for (int p = 0; p < 4; p++) acc[i][p] = 0ull;

    float sacc[8];
    #pragma unroll
    for (int q = 0; q < 8; q++) sacc[q] = 0.0f;

    int t32 = tid & 31;
    int trow = tid >> 5;

    for (int b0 = 0; b0 < BATCH; b0 += 32) {
        __syncthreads();
        // stage x tile [32 b][128 d], coalesced float4
        #pragma unroll
        for (int q = 0; q < 4; q++) {
            int row = trow + 8 * q;
            float4 v = *(const float4*)&x[(size_t)(b0 + row) * FEATS + d0 + t32 * 4];
            *(float4*)&xu[row][t32 * 4] = v;
        }
        // generate L tile: b = lane, n = warp + 8q
        {
            int bmu = g_bmu[b0 + lane];
            float bi = (float)(bmu >> 6);
            float bj = (float)(bmu & 63);
            #pragma unroll
            for (int q = 0; q < 8; q++) {
                int n = warp + 8 * q;
                int gn = n0 + n;
                float di = (float)(gn >> 6) - bi;
                float dj = (float)(gn & 63) - bj;
                float d2 = di * di + dj * dj;
                float v = (d2 <= r2) ? lr * __expf(-d2 * inv2r2) : 0.0f;
                Lt[lane][n] = v;
                // warp-reduce column sum (all b in chunk for node n)
                #pragma unroll
                for (int o = 16; o; o >>= 1) v += __shfl_xor_sync(0xFFFFFFFFu, v, o);
                sacc[q] += v;   // meaningful on all lanes; used from lane 0
            }
        }
        __syncthreads();

        #pragma unroll
        for (int k = 0; k < 32; k++) {
            u64 ld[4];
            #pragma unroll
            for (int i = 0; i < 4; i++) ld[i] = dup2(Lt[k][ty * 4 + i]);
            const ulonglong2* xp = (const ulonglong2*)&xu[k][tx * 8];
            ulonglong2 xA = xp[0], xB = xp[1];
            #pragma unroll
            for (int i = 0; i < 4; i++) {
                ffma2(acc[i][0], ld[i], xA.x);
                ffma2(acc[i][1], ld[i], xA.y);
                ffma2(acc[i][2], ld[i], xB.x);
                ffma2(acc[i][3], ld[i], xB.y);
            }
        }
    }

    if (lane == 0) {
        #pragma unroll
        for (int q = 0; q < 8; q++) s_sm[warp + 8 * q] = sacc[q];
    }
    __syncthreads();

    const float invB = 1.0f / (float)BATCH;
    #pragma unroll
    for (int i = 0; i < 4; i++) {
        int n = n0 + ty * 4 + i;
        float s = s_sm[ty * 4 + i];
        size_t base = (size_t)n * FEATS + d0 + tx * 8;
        #pragma unroll
        for (int p = 0; p < 4; p++) {
            float2 a = unpk(acc[i][p]);
            float2 wv = *(const float2*)&w[base + 2 * p];
            float2 o;
            o.x = wv.x + (a.x - s * wv.x) * invB;
            o.y = wv.y + (a.y - s * wv.y) * invB;
            *(float2*)&out[base + 2 * p] = o;
        }
    }
}

// ============================================================
extern "C" void kernel_launch(void* const* d_in, const int* in_sizes, int n_in,
                              void* d_out, int out_size) {
    const float* x = nullptr;
    const float* w = nullptr;
    const int* iter = nullptr;
    for (int i = 0; i < n_in; i++) {
        if (in_sizes[i] == BATCH * FEATS)      x = (const float*)d_in[i];
        else if (in_sizes[i] == NODES * FEATS) w = (const float*)d_in[i];
        else if (in_sizes[i] == 1)             iter = (const int*)d_in[i];
    }
    float* out = (float*)d_out;

    k_init<<<4, 256>>>(iter);
    k_w2<<<NODES / 8, 256>>>(w);
    dim3 g1(NODES / 128, BATCH / 128);
    k_bmu<<<g1, 256>>>(x, w);
    k_finalize<<<4, 256>>>(out, out_size);
    k_update<<<NODES / 64 * (FEATS / 128), 256>>>(x, w, out);
}

// round 4
// speedup vs baseline: 2.8832x; 2.8832x over previous
#include <cuda_runtime.h>
#include <cuda_fp16.h>
#include <stdint.h>

// ---- SOM constants (match reference) ----
#define NODES 4096
#define FEATS 256
#define BATCH 1024
#define SIGMA_F 70.4f        // max(M,N) * 1.1
#define TOTAL_ITER_F 100000.0f

typedef unsigned long long u64;

// ---- device scratch (no allocations allowed) ----
__device__ u64   g_best[BATCH];
__device__ float g_w2[NODES];
__device__ float g_params[3];   // [0]=lr, [1]=1/(2 r^2), [2]=r^2
// split fp16 operands: xa = [xh | xh | xl] (K=768), wb = [wh | wl | wh]
__device__ __align__(16) __half g_xa[BATCH * 768];
__device__ __align__(16) __half g_wb[NODES * 768];
__device__ __align__(16) __half g_xt[FEATS * BATCH];   // x transposed, fp16

// ---- PTX helpers (all baseline sm_80/75 features) ----
__device__ __forceinline__ uint32_t smem_u32(const void* p) {
    uint32_t a;
    asm("{ .reg .u64 t; cvta.to.shared.u64 t, %1; cvt.u32.u64 %0, t; }"
        : "=r"(a) : "l"(p));
    return a;
}
__device__ __forceinline__ void cp16(uint32_t dst, const void* src) {
    asm volatile("cp.async.cg.shared.global [%0], [%1], 16;"
                 :: "r"(dst), "l"(src));
}
#define CP_COMMIT() asm volatile("cp.async.commit_group;" ::: "memory")
#define CP_WAIT0()  asm volatile("cp.async.wait_group 0;" ::: "memory")

__device__ __forceinline__ void ldsm4(uint32_t* r, uint32_t addr) {
    asm volatile("ldmatrix.sync.aligned.m8n8.x4.shared.b16 {%0,%1,%2,%3}, [%4];"
                 : "=r"(r[0]), "=r"(r[1]), "=r"(r[2]), "=r"(r[3]) : "r"(addr));
}
__device__ __forceinline__ void mma16816(float* c, const uint32_t* a,
                                         const uint32_t* b) {
    asm volatile(
        "mma.sync.aligned.m16n8k16.row.col.f32.f16.f16.f32 "
        "{%0,%1,%2,%3}, {%4,%5,%6,%7}, {%8,%9}, {%0,%1,%2,%3};"
        : "+f"(c[0]), "+f"(c[1]), "+f"(c[2]), "+f"(c[3])
        : "r"(a[0]), "r"(a[1]), "r"(a[2]), "r"(a[3]), "r"(b[0]), "r"(b[1]));
}
__device__ __forceinline__ u64 packkey(float d, int n) {
    unsigned u = __float_as_uint(d);
    u = (u & 0x80000000u) ? ~u : (u | 0x80000000u);
    return ((u64)u << 32) | (unsigned)n;
}

// ============================================================
// K1: reset argmin keys + decay params
// ============================================================
__global__ void k_prep(const int* __restrict__ iter) {
    int t = blockIdx.x * blockDim.x + threadIdx.x;
    if (t < BATCH) g_best[t] = 0xFFFFFFFFFFFFFFFFull;
    if (t == 0) {
        float lambda_g = TOTAL_ITER_F / SIGMA_F;
        float decay    = expf(-(float)iter[0] / lambda_g);
        float radius   = SIGMA_F * decay + 1e-6f;
        g_params[0] = 0.5f * decay;
        g_params[1] = 1.0f / (2.0f * radius * radius);
        g_params[2] = radius * radius;
    }
}

// ============================================================
// K2: fp16 hi/lo split of w and x (+ w2). Warp per row.
// ============================================================
__device__ __forceinline__ void st4h(__half* p, float a, float b, float c, float d) {
    ((__half2*)p)[0] = __floats2half2_rn(a, b);
    ((__half2*)p)[1] = __floats2half2_rn(c, d);
}
__global__ void k_split(const float* __restrict__ x, const float* __restrict__ w) {
    int bid = blockIdx.x;
    int warp = threadIdx.x >> 5, lane = threadIdx.x & 31;
    if (bid < NODES / 8) {
        int n = bid * 8 + warp;
        const float4* row = (const float4*)(w + (size_t)n * FEATS);
        float s = 0.0f;
        #pragma unroll
        for (int i = 0; i < 2; i++) {
            float4 v = row[lane + 32 * i];
            int c = (lane + 32 * i) * 4;
            s += v.x * v.x + v.y * v.y + v.z * v.z + v.w * v.w;
            float hx = __half2float(__float2half_rn(v.x));
            float hy = __half2float(__float2half_rn(v.y));
            float hz = __half2float(__float2half_rn(v.z));
            float hw = __half2float(__float2half_rn(v.w));
            st4h(g_wb + n * 768 + c,       hx, hy, hz, hw);
            st4h(g_wb + n * 768 + 256 + c, v.x - hx, v.y - hy, v.z - hz, v.w - hw);
            st4h(g_wb + n * 768 + 512 + c, hx, hy, hz, hw);
        }
        #pragma unroll
        for (int o = 16; o; o >>= 1) s += __shfl_xor_sync(0xFFFFFFFFu, s, o);
        if (lane == 0) g_w2[n] = s;
    } else {
        int r = (bid - NODES / 8) * 8 + warp;
        const float4* row = (const float4*)(x + (size_t)r * FEATS);
        #pragma unroll
        for (int i = 0; i < 2; i++) {
            float4 v = row[lane + 32 * i];
            int c = (lane + 32 * i) * 4;
            float hx = __half2float(__float2half_rn(v.x));
            float hy = __half2float(__float2half_rn(v.y));
            float hz = __half2float(__float2half_rn(v.z));
            float hw = __half2float(__float2half_rn(v.w));
            st4h(g_xa + r * 768 + c,       hx, hy, hz, hw);
            st4h(g_xa + r * 768 + 256 + c, hx, hy, hz, hw);
            st4h(g_xa + r * 768 + 512 + c, v.x - hx, v.y - hy, v.z - hz, v.w - hw);
        }
    }
}

// ============================================================
// K3: transpose x -> g_xt [256 d][1024 b] fp16 (64x64 tiles)
// ============================================================
__global__ void k_xt(const float* __restrict__ x) {
    __shared__ float s[64][65];
    int bx = blockIdx.x;                 // 16 b-tiles x 4 d-tiles
    int b0 = (bx >> 2) * 64, d0 = (bx & 3) * 64;
    int t = threadIdx.x;
    #pragma unroll
    for (int q = 0; q < 16; q++) {
        int e = q * 256 + t;
        int br = e >> 6, dc = e & 63;
        s[br][dc] = x[(size_t)(b0 + br) * FEATS + d0 + dc];
    }
    __syncthreads();
    #pragma unroll
    for (int q = 0; q < 16; q++) {
        int e = q * 256 + t;
        int dr = e >> 6, bc = e & 63;
        g_xt[(size_t)(d0 + dr) * BATCH + b0 + bc] = __float2half_rn(s[bc][dr]);
    }
}

// ============================================================
// K4: BMU GEMM via HMMA. CTA tile 128m x 256n, 512 thr (16 warps,
// warp tile 32m x 64n). K=768 in 12 chunks of 64, cp.async double-buf.
// dist = w2[n] - 2*dot; fused argmin -> packed atomicMin.
// smem rows padded to 144B for conflict-free ldmatrix.
// ============================================================
#define ASZ (128 * 144)
#define BSZ (256 * 144)
#define OFF_A 1024
#define OFF_B (1024 + 2 * ASZ)
#define SM_BMU (OFF_B + 2 * BSZ)

__device__ __forceinline__ void stage_bmu(uint32_t sb, int buf, int kc,
                                          int m0, int n0, int t) {
    uint32_t adst = sb + OFF_A + buf * ASZ;
    #pragma unroll
    for (int q = 0; q < 2; q++) {
        int g = t + 512 * q; int r = g >> 3, c = g & 7;
        cp16(adst + r * 144 + c * 16, g_xa + (size_t)(m0 + r) * 768 + kc * 64 + c * 8);
    }
    uint32_t bdst = sb + OFF_B + buf * BSZ;
    #pragma unroll
    for (int q = 0; q < 4; q++) {
        int g = t + 512 * q; int r = g >> 3, c = g & 7;
        cp16(bdst + r * 144 + c * 16, g_wb + (size_t)(n0 + r) * 768 + kc * 64 + c * 8);
    }
    CP_COMMIT();
}

__global__ void __launch_bounds__(512, 1) k_bmu() {
    extern __shared__ char sm[];
    uint32_t sb = smem_u32(sm);
    float* w2s = (float*)sm;
    int t = threadIdx.x, lane = t & 31, warp = t >> 5;
    int wm = warp >> 2, wn = warp & 3;       // 4x4 warp grid
    int n0 = blockIdx.x * 256;
    int m0 = blockIdx.y * 128;

    if (t < 256) w2s[t] = g_w2[n0 + t];

    float c[2][8][4];
    #pragma unroll
    for (int i = 0; i < 2; i++)
        #pragma unroll
        for (int j = 0; j < 8; j++)
            #pragma unroll
            for (int q = 0; q < 4; q++) c[i][j][q] = 0.0f;

    uint32_t aoff = (uint32_t)((lane & 15) * 144 + (lane >> 4) * 16);
    uint32_t boff = (uint32_t)(((lane & 7) + ((lane >> 4) << 3)) * 144
                               + (((lane >> 3) & 1) << 4));

    stage_bmu(sb, 0, 0, m0, n0, t);
    for (int ch = 0; ch < 12; ch++) {
        CP_WAIT0();
        __syncthreads();
        if (ch + 1 < 12) stage_bmu(sb, (ch + 1) & 1, ch + 1, m0, n0, t);

        uint32_t Ab = sb + OFF_A + (ch & 1) * ASZ + (wm * 32) * 144 + aoff;
        uint32_t Bb = sb + OFF_B + (ch & 1) * BSZ + (wn * 64) * 144 + boff;
        #pragma unroll
        for (int k16 = 0; k16 < 4; k16++) {
            uint32_t a[2][4], b[4][4];
            #pragma unroll
            for (int im = 0; im < 2; im++)
                ldsm4(a[im], Ab + im * 16 * 144 + k16 * 32);
            #pragma unroll
            for (int j2 = 0; j2 < 4; j2++)
                ldsm4(b[j2], Bb + j2 * 16 * 144 + k16 * 32);
            #pragma unroll
            for (int im = 0; im < 2; im++)
                #pragma unroll
                for (int j2 = 0; j2 < 4; j2++) {
                    mma16816(c[im][2 * j2],     a[im], b[j2]);
                    mma16816(c[im][2 * j2 + 1], a[im], b[j2] + 2);
                }
        }
        __syncthreads();
    }

    // fused argmin epilogue
    #pragma unroll
    for (int im = 0; im < 2; im++) {
        #pragma unroll
        for (int h = 0; h < 2; h++) {
            float best = __int_as_float(0x7F800000);
            int bestn = 0;
            #pragma unroll
            for (int j8 = 0; j8 < 8; j8++) {
                int nl = wn * 64 + j8 * 8 + 2 * (lane & 3);
                float v0 = w2s[nl]     - 2.0f * c[im][j8][2 * h];
                float v1 = w2s[nl + 1] - 2.0f * c[im][j8][2 * h + 1];
                if (v0 < best) { best = v0; bestn = nl; }
                if (v1 < best) { best = v1; bestn = nl + 1; }
            }
            #pragma unroll
            for (int o = 1; o <= 2; o <<= 1) {
                float od = __shfl_xor_sync(0xFFFFFFFFu, best, o);
                int   on = __shfl_xor_sync(0xFFFFFFFFu, bestn, o);
                if (od < best || (od == best && on < bestn)) { best = od; bestn = on; }
            }
            if ((lane & 3) == 0) {
                int m = m0 + wm * 32 + im * 16 + h * 8 + (lane >> 2);
                atomicMin(&g_best[m], packkey(best, n0 + bestn));
            }
        }
    }
}

// ============================================================
// K5: update GEMM via HMMA. C[n,d] = sum_b L[n,b]*Xt[d,b].
// CTA tile 64n x 128d, 256 thr (8 warps: 2n x 4d, warp 32x32).
// L tile (64n x 64b) generated per chunk (fp32 exp -> fp16).
// out = w + (C - S*w)/B; bmu floats appended.
// ============================================================
__global__ void __launch_bounds__(256, 1) k_update(const float* __restrict__ w,
                                                   float* __restrict__ out,
                                                   int out_size) {
    __shared__ float s_sm[64];
    __shared__ float s_part[256];
    __shared__ __align__(16) char Ls[64 * 144];
    __shared__ __align__(16) char Xs[2][128 * 144];

    uint32_t sbL = smem_u32(Ls);
    uint32_t sbX = smem_u32(Xs);

    int t = threadIdx.x, lane = t & 31, warp = t >> 5;
    int wn = warp >> 2, wd = warp & 3;       // 2 x 4 warp grid
    int bx = blockIdx.x;
    int n0 = (bx >> 1) * 64;
    int d0 = (bx & 1) * 128;

    float lr = g_params[0], inv2r2 = g_params[1], r2 = g_params[2];

    int n_l = t & 63;
    int gn = n0 + n_l;
    int ni = gn >> 6, nj = gn & 63;
    float s_local = 0.0f;

    float c[2][4][4];
    #pragma unroll
    for (int i = 0; i < 2; i++)
        #pragma unroll
        for (int j = 0; j < 4; j++)
            #pragma unroll
            for (int q = 0; q < 4; q++) c[i][j][q] = 0.0f;

    uint32_t aoff = (uint32_t)((lane & 15) * 144 + (lane >> 4) * 16);
    uint32_t boff = (uint32_t)(((lane & 7) + ((lane >> 4) << 3)) * 144
                               + (((lane >> 3) & 1) << 4));

    // prefetch X chunk 0
    {
        #pragma unroll
        for (int q = 0; q < 4; q++) {
            int g = t + 256 * q; int r = g >> 3, cc = g & 7;
            cp16(sbX + r * 144 + cc * 16, g_xt + (size_t)(d0 + r) * BATCH + cc * 8);
        }
        CP_COMMIT();
    }

    for (int ch = 0; ch < 16; ch++) {
        int bc0 = ch * 64;
        CP_WAIT0();
        __syncthreads();
        if (ch + 1 < 16) {
            uint32_t xdst = sbX + ((ch + 1) & 1) * (128 * 144);
            #pragma unroll
            for (int q = 0; q < 4; q++) {
                int g = t + 256 * q; int r = g >> 3, cc = g & 7;
                cp16(xdst + r * 144 + cc * 16,
                     g_xt + (size_t)(d0 + r) * BATCH + (ch + 1) * 64 + cc * 8);
            }
            CP_COMMIT();
        }
        // generate L tile [64n][64b]
        {
            int bq = t >> 6;   // 0..3
            __half* Lh = (__half*)Ls;
            #pragma unroll
            for (int j = 0; j < 16; j++) {
                int bb = bq + 4 * j;
                int bmu = (int)(unsigned)(g_best[bc0 + bb] & 0xFFFFFFFFull);
                int di = ni - (bmu >> 6);
                int dj = nj - (bmu & 63);
                float d2 = (float)(di * di + dj * dj);
                float v = (d2 <= r2) ? lr * __expf(-d2 * inv2r2) : 0.0f;
                Lh[n_l * 72 + bb] = __float2half_rn(v);
                s_local += v;
            }
        }
        __syncthreads();

        uint32_t Ab = sbL + (wn * 32) * 144 + aoff;
        uint32_t Bb = sbX + (ch & 1) * (128 * 144) + (wd * 32) * 144 + boff;
        #pragma unroll
        for (int k16 = 0; k16 < 4; k16++) {
            uint32_t a[2][4], b[2][4];
            #pragma unroll
            for (int im = 0; im < 2; im++)
                ldsm4(a[im], Ab + im * 16 * 144 + k16 * 32);
            #pragma unroll
            for (int j2 = 0; j2 < 2; j2++)
                ldsm4(b[j2], Bb + j2 * 16 * 144 + k16 * 32);
            #pragma unroll
            for (int im = 0; im < 2; im++)
                #pragma unroll
                for (int jd = 0; jd < 4; jd++)
                    mma16816(c[im][jd], a[im], b[jd >> 1] + (jd & 1) * 2);
        }
        __syncthreads();
    }

    // reduce column sums S[n]
    s_part[t] = s_local;
    __syncthreads();
    if (t < 64)
        s_sm[t] = s_part[t] + s_part[t + 64] + s_part[t + 128] + s_part[t + 192];
    __syncthreads();

    const float invB = 1.0f / (float)BATCH;
    #pragma unroll
    for (int im = 0; im < 2; im++) {
        #pragma unroll
        for (int h = 0; h < 2; h++) {
            int nl = wn * 32 + im * 16 + h * 8 + (lane >> 2);
            int n = n0 + nl;
            float s = s_sm[nl];
            #pragma unroll
            for (int jd = 0; jd < 4; jd++) {
                int d = d0 + wd * 32 + jd * 8 + 2 * (lane & 3);
                size_t idx = (size_t)n * FEATS + d;
                float2 wv = *(const float2*)&w[idx];
                float a0 = c[im][jd][2 * h], a1 = c[im][jd][2 * h + 1];
                float2 o;
                o.x = wv.x + (a0 - s * wv.x) * invB;
                o.y = wv.y + (a1 - s * wv.y) * invB;
                *(float2*)&out[idx] = o;
            }
        }
    }

    // emit bmu indices (as float) after the map if there is room
    if (bx < 4 && out_size >= NODES * FEATS + BATCH) {
        int b = bx * 256 + t;
        out[NODES * FEATS + b] =
            (float)(unsigned)(g_best[b] & 0xFFFFFFFFull);
    }
}

// ============================================================
extern "C" void kernel_launch(void* const* d_in, const int* in_sizes, int n_in,
                              void* d_out, int out_size) {
    const float* x = nullptr;
    const float* w = nullptr;
    const int* iter = nullptr;
    for (int i = 0; i < n_in; i++) {
        if (in_sizes[i] == BATCH * FEATS)      x = (const float*)d_in[i];
        else if (in_sizes[i] == NODES * FEATS) w = (const float*)d_in[i];
        else if (in_sizes[i] == 1)             iter = (const int*)d_in[i];
    }
    float* out = (float*)d_out;

    cudaFuncSetAttribute(k_bmu, cudaFuncAttributeMaxDynamicSharedMemorySize, SM_BMU);

    k_prep<<<4, 256>>>(iter);
    k_split<<<NODES / 8 + BATCH / 8, 256>>>(x, w);
    k_xt<<<64, 256>>>(x);
    dim3 gb(NODES / 256, BATCH / 128);
    k_bmu<<<gb, 512, SM_BMU>>>();
    k_update<<<(NODES / 64) * (FEATS / 128), 256>>>(w, out, out_size);
}

// round 5
// speedup vs baseline: 3.0738x; 1.0661x over previous
#include <cuda_runtime.h>
#include <cuda_fp16.h>
#include <stdint.h>

// ---- SOM constants (match reference) ----
#define NODES 4096
#define FEATS 256
#define BATCH 1024
#define SIGMA_F 70.4f        // max(M,N) * 1.1
#define TOTAL_ITER_F 100000.0f

typedef unsigned long long u64;

// ---- device scratch (no allocations allowed) ----
__device__ u64   g_best[BATCH];
__device__ float g_w2[NODES];
__device__ float g_params[3];   // [0]=lr, [1]=1/(2 r^2), [2]=r^2
__device__ __align__(16) __half g_xh[BATCH * FEATS];
__device__ __align__(16) __half g_xl[BATCH * FEATS];
__device__ __align__(16) __half g_wh[NODES * FEATS];
__device__ __align__(16) __half g_wl[NODES * FEATS];
__device__ __align__(16) __half g_xt[FEATS * BATCH];   // x transposed, fp16

// ---- PTX helpers ----
__device__ __forceinline__ uint32_t smem_u32(const void* p) {
    uint32_t a;
    asm("{ .reg .u64 t; cvta.to.shared.u64 t, %1; cvt.u32.u64 %0, t; }"
        : "=r"(a) : "l"(p));
    return a;
}
__device__ __forceinline__ void cp16(uint32_t dst, const void* src) {
    asm volatile("cp.async.cg.shared.global [%0], [%1], 16;"
                 :: "r"(dst), "l"(src));
}
#define CP_COMMIT() asm volatile("cp.async.commit_group;" ::: "memory")
#define CP_WAIT0()  asm volatile("cp.async.wait_group 0;" ::: "memory")

__device__ __forceinline__ void ldsm4(uint32_t* r, uint32_t addr) {
    asm volatile("ldmatrix.sync.aligned.m8n8.x4.shared.b16 {%0,%1,%2,%3}, [%4];"
                 : "=r"(r[0]), "=r"(r[1]), "=r"(r[2]), "=r"(r[3]) : "r"(addr));
}
__device__ __forceinline__ void mma16816(float* c, const uint32_t* a,
                                         const uint32_t* b) {
    asm volatile(
        "mma.sync.aligned.m16n8k16.row.col.f32.f16.f16.f32 "
        "{%0,%1,%2,%3}, {%4,%5,%6,%7}, {%8,%9}, {%0,%1,%2,%3};"
        : "+f"(c[0]), "+f"(c[1]), "+f"(c[2]), "+f"(c[3])
        : "r"(a[0]), "r"(a[1]), "r"(a[2]), "r"(a[3]), "r"(b[0]), "r"(b[1]));
}
__device__ __forceinline__ u64 packkey(float d, int n) {
    unsigned u = __float_as_uint(d);
    u = (u & 0x80000000u) ? ~u : (u | 0x80000000u);
    return ((u64)u << 32) | (unsigned)n;
}

// ============================================================
// K1: fused prep. Blocks [0,512): w split+w2; [512,640): x split;
// [640,704): x transpose (+ g_best reset + params in first 4).
// ============================================================
__device__ __forceinline__ void st4h(__half* p, float a, float b, float c, float d) {
    ((__half2*)p)[0] = __floats2half2_rn(a, b);
    ((__half2*)p)[1] = __floats2half2_rn(c, d);
}

__global__ void __launch_bounds__(256) k_prep_all(const float* __restrict__ x,
                                                  const float* __restrict__ w,
                                                  const int* __restrict__ iter) {
    int bid = blockIdx.x;
    int t = threadIdx.x;
    int warp = t >> 5, lane = t & 31;

    if (bid < 512) {                       // w rows: split + w2
        int n = bid * 8 + warp;
        const float4* row = (const float4*)(w + (size_t)n * FEATS);
        float s = 0.0f;
        #pragma unroll
        for (int i = 0; i < 2; i++) {
            float4 v = row[lane + 32 * i];
            int c = (lane + 32 * i) * 4;
            s += v.x * v.x + v.y * v.y + v.z * v.z + v.w * v.w;
            float hx = __half2float(__float2half_rn(v.x));
            float hy = __half2float(__float2half_rn(v.y));
            float hz = __half2float(__float2half_rn(v.z));
            float hw = __half2float(__float2half_rn(v.w));
            st4h(g_wh + n * FEATS + c, hx, hy, hz, hw);
            st4h(g_wl + n * FEATS + c, v.x - hx, v.y - hy, v.z - hz, v.w - hw);
        }
        #pragma unroll
        for (int o = 16; o; o >>= 1) s += __shfl_xor_sync(0xFFFFFFFFu, s, o);
        if (lane == 0) g_w2[n] = s;
    } else if (bid < 640) {                // x rows: split
        int r = (bid - 512) * 8 + warp;
        const float4* row = (const float4*)(x + (size_t)r * FEATS);
        #pragma unroll
        for (int i = 0; i < 2; i++) {
            float4 v = row[lane + 32 * i];
            int c = (lane + 32 * i) * 4;
            float hx = __half2float(__float2half_rn(v.x));
            float hy = __half2float(__float2half_rn(v.y));
            float hz = __half2float(__float2half_rn(v.z));
            float hw = __half2float(__float2half_rn(v.w));
            st4h(g_xh + r * FEATS + c, hx, hy, hz, hw);
            st4h(g_xl + r * FEATS + c, v.x - hx, v.y - hy, v.z - hz, v.w - hw);
        }
    } else {                               // x transpose tiles
        __shared__ float s[64][65];
        int bx2 = bid - 640;
        if (bx2 < 4) {
            g_best[bx2 * 256 + t] = 0xFFFFFFFFFFFFFFFFull;
            if (bx2 == 0 && t == 0) {
                float lambda_g = TOTAL_ITER_F / SIGMA_F;
                float decay    = expf(-(float)iter[0] / lambda_g);
                float radius   = SIGMA_F * decay + 1e-6f;
                g_params[0] = 0.5f * decay;
                g_params[1] = 1.0f / (2.0f * radius * radius);
                g_params[2] = radius * radius;
            }
        }
        int b0 = (bx2 >> 2) * 64, d0 = (bx2 & 3) * 64;
        #pragma unroll
        for (int q = 0; q < 16; q++) {
            int e = q * 256 + t;
            int br = e >> 6, dc = e & 63;
            s[br][dc] = x[(size_t)(b0 + br) * FEATS + d0 + dc];
        }
        __syncthreads();
        #pragma unroll
        for (int q = 0; q < 16; q++) {
            int e = q * 256 + t;
            int dr = e >> 6, bc = e & 63;
            g_xt[(size_t)(d0 + dr) * BATCH + b0 + bc] = __float2half_rn(s[bc][dr]);
        }
    }
}

// ============================================================
// K2: BMU GEMM via HMMA (structure proven in R4).
// CTA tile 128m x 256n, 512 thr (16 warps 4x4, warp 32m x 64n).
// K = 3 terms x 256 (AhBh + AhBl + AlBh), 12 chunks of 64,
// sources selected by pointer per chunk (no materialized concat).
// ============================================================
#define ASZ (128 * 144)
#define BSZ (256 * 144)
#define OFF_A 1024
#define OFF_B (1024 + 2 * ASZ)
#define SM_BMU (OFF_B + 2 * BSZ)

__device__ __forceinline__ void stage_bmu(uint32_t sb, int buf, int ch,
                                          int m0, int n0, int t) {
    int term = ch >> 2;
    int kk = (ch & 3) * 64;
    const __half* asrc = (term < 2) ? g_xh : g_xl;
    const __half* bsrc = (term == 1) ? g_wl : g_wh;
    uint32_t adst = sb + OFF_A + buf * ASZ;
    #pragma unroll
    for (int q = 0; q < 2; q++) {
        int g = t + 512 * q; int r = g >> 3, c = g & 7;
        cp16(adst + r * 144 + c * 16, asrc + (size_t)(m0 + r) * FEATS + kk + c * 8);
    }
    uint32_t bdst = sb + OFF_B + buf * BSZ;
    #pragma unroll
    for (int q = 0; q < 4; q++) {
        int g = t + 512 * q; int r = g >> 3, c = g & 7;
        cp16(bdst + r * 144 + c * 16, bsrc + (size_t)(n0 + r) * FEATS + kk + c * 8);
    }
    CP_COMMIT();
}

__global__ void __launch_bounds__(512, 1) k_bmu() {
    extern __shared__ char sm[];
    uint32_t sb = smem_u32(sm);
    float* w2s = (float*)sm;
    int t = threadIdx.x, lane = t & 31, warp = t >> 5;
    int wm = warp >> 2, wn = warp & 3;
    int n0 = blockIdx.x * 256;
    int m0 = blockIdx.y * 128;

    if (t < 256) w2s[t] = g_w2[n0 + t];

    float c[2][8][4];
    #pragma unroll
    for (int i = 0; i < 2; i++)
        #pragma unroll
        for (int j = 0; j < 8; j++)
            #pragma unroll
            for (int q = 0; q < 4; q++) c[i][j][q] = 0.0f;

    uint32_t aoff = (uint32_t)((lane & 15) * 144 + (lane >> 4) * 16);
    uint32_t boff = (uint32_t)(((lane & 7) + ((lane >> 4) << 3)) * 144
                               + (((lane >> 3) & 1) << 4));

    stage_bmu(sb, 0, 0, m0, n0, t);
    for (int ch = 0; ch < 12; ch++) {
        CP_WAIT0();
        __syncthreads();
        if (ch + 1 < 12) stage_bmu(sb, (ch + 1) & 1, ch + 1, m0, n0, t);

        uint32_t Ab = sb + OFF_A + (ch & 1) * ASZ + (wm * 32) * 144 + aoff;
        uint32_t Bb = sb + OFF_B + (ch & 1) * BSZ + (wn * 64) * 144 + boff;
        #pragma unroll
        for (int k16 = 0; k16 < 4; k16++) {
            uint32_t a[2][4], b[4][4];
            #pragma unroll
            for (int im = 0; im < 2; im++)
                ldsm4(a[im], Ab + im * 16 * 144 + k16 * 32);
            #pragma unroll
            for (int j2 = 0; j2 < 4; j2++)
                ldsm4(b[j2], Bb + j2 * 16 * 144 + k16 * 32);
            #pragma unroll
            for (int im = 0; im < 2; im++)
                #pragma unroll
                for (int j2 = 0; j2 < 4; j2++) {
                    mma16816(c[im][2 * j2],     a[im], b[j2]);
                    mma16816(c[im][2 * j2 + 1], a[im], b[j2] + 2);
                }
        }
        __syncthreads();
    }

    // fused argmin epilogue
    #pragma unroll
    for (int im = 0; im < 2; im++) {
        #pragma unroll
        for (int h = 0; h < 2; h++) {
            float best = __int_as_float(0x7F800000);
            int bestn = 0;
            #pragma unroll
            for (int j8 = 0; j8 < 8; j8++) {
                int nl = wn * 64 + j8 * 8 + 2 * (lane & 3);
                float v0 = w2s[nl]     - 2.0f * c[im][j8][2 * h];
                float v1 = w2s[nl + 1] - 2.0f * c[im][j8][2 * h + 1];
                if (v0 < best) { best = v0; bestn = nl; }
                if (v1 < best) { best = v1; bestn = nl + 1; }
            }
            #pragma unroll
            for (int o = 1; o <= 2; o <<= 1) {
                float od = __shfl_xor_sync(0xFFFFFFFFu, best, o);
                int   on = __shfl_xor_sync(0xFFFFFFFFu, bestn, o);
                if (od < best || (od == best && on < bestn)) { best = od; bestn = on; }
            }
            if ((lane & 3) == 0) {
                int m = m0 + wm * 32 + im * 16 + h * 8 + (lane >> 2);
                atomicMin(&g_best[m], packkey(best, n0 + bestn));
            }
        }
    }
}

// ============================================================
// K3: update GEMM via HMMA, 512 thr. C[n,d] = sum_b L[n,b]*Xt[d,b].
// CTA tile 64n x 128d, warps 4n x 4d (warp 16n x 32d), grid 128.
// L tile regenerated per 64-b chunk (fp32 exp -> fp16).
// ============================================================
__global__ void __launch_bounds__(512, 1) k_update(const float* __restrict__ w,
                                                   float* __restrict__ out,
                                                   int out_size) {
    __shared__ float s_sm[64];
    __shared__ float s_part[512];
    __shared__ __align__(16) __half Ls[64 * 72];
    __shared__ __align__(16) __half Xs[2][128 * 72];

    uint32_t sbL = smem_u32(Ls);
    uint32_t sbX = smem_u32(Xs);

    int t = threadIdx.x, lane = t & 31, warp = t >> 5;
    int wn = warp >> 2, wd = warp & 3;
    int bx = blockIdx.x;
    int n0 = (bx >> 1) * 64;
    int d0 = (bx & 1) * 128;

    float lr = g_params[0], inv2r2 = g_params[1], r2 = g_params[2];

    int n_l = t & 63;
    int gn = n0 + n_l;
    int ni = gn >> 6, nj = gn & 63;
    int bgrp = t >> 6;          // 0..7
    float s_local = 0.0f;

    float c[4][4];
    #pragma unroll
    for (int j = 0; j < 4; j++)
        #pragma unroll
        for (int q = 0; q < 4; q++) c[j][q] = 0.0f;

    uint32_t aoff = (uint32_t)((lane & 15) * 144 + (lane >> 4) * 16);
    uint32_t boff = (uint32_t)(((lane & 7) + ((lane >> 4) << 3)) * 144
                               + (((lane >> 3) & 1) << 4));

    // prefetch X chunk 0 (128 rows x 8 granules = 1024; 2 per thread)
    #pragma unroll
    for (int q = 0; q < 2; q++) {
        int g = t + 512 * q; int r = g >> 3, cc = g & 7;
        cp16(sbX + r * 144 + cc * 16, g_xt + (size_t)(d0 + r) * BATCH + cc * 8);
    }
    CP_COMMIT();

    for (int ch = 0; ch < 16; ch++) {
        int bc0 = ch * 64;
        CP_WAIT0();
        __syncthreads();
        if (ch + 1 < 16) {
            uint32_t xdst = sbX + ((ch + 1) & 1) * (128 * 144);
            #pragma unroll
            for (int q = 0; q < 2; q++) {
                int g = t + 512 * q; int r = g >> 3, cc = g & 7;
                cp16(xdst + r * 144 + cc * 16,
                     g_xt + (size_t)(d0 + r) * BATCH + (ch + 1) * 64 + cc * 8);
            }
            CP_COMMIT();
        }
        // generate L tile [64n][64b]: thread handles n = t&63, b = bgrp+8j
        #pragma unroll
        for (int j = 0; j < 8; j++) {
            int bb = bgrp + 8 * j;
            int bmu = (int)(unsigned)(g_best[bc0 + bb] & 0xFFFFFFFFull);
            int di = ni - (bmu >> 6);
            int dj = nj - (bmu & 63);
            float d2 = (float)(di * di + dj * dj);
            float v = (d2 <= r2) ? lr * __expf(-d2 * inv2r2) : 0.0f;
            Ls[n_l * 72 + bb] = __float2half_rn(v);
            s_local += v;
        }
        __syncthreads();

        uint32_t Ab = sbL + (wn * 16) * 144 + aoff;
        uint32_t Bb = sbX + (ch & 1) * (128 * 144) + (wd * 32) * 144 + boff;
        #pragma unroll
        for (int k16 = 0; k16 < 4; k16++) {
            uint32_t a[4], b[2][4];
            ldsm4(a, Ab + k16 * 32);
            #pragma unroll
            for (int j2 = 0; j2 < 2; j2++)
                ldsm4(b[j2], Bb + j2 * 16 * 144 + k16 * 32);
            #pragma unroll
            for (int jd = 0; jd < 4; jd++)
                mma16816(c[jd], a, b[jd >> 1] + (jd & 1) * 2);
        }
        __syncthreads();
    }

    // reduce column sums S[n] over the 8 b-groups
    s_part[t] = s_local;
    __syncthreads();
    if (t < 64) {
        float s = 0.0f;
        #pragma unroll
        for (int g = 0; g < 8; g++) s += s_part[t + 64 * g];
        s_sm[t] = s;
    }
    __syncthreads();

    const float invB = 1.0f / (float)BATCH;
    #pragma unroll
    for (int h = 0; h < 2; h++) {
        int nl = wn * 16 + h * 8 + (lane >> 2);
        int n = n0 + nl;
        float s = s_sm[nl];
        #pragma unroll
        for (int jd = 0; jd < 4; jd++) {
            int d = d0 + wd * 32 + jd * 8 + 2 * (lane & 3);
            size_t idx = (size_t)n * FEATS + d;
            float2 wv = *(const float2*)&w[idx];
            float a0 = c[jd][2 * h], a1 = c[jd][2 * h + 1];
            float2 o;
            o.x = wv.x + (a0 - s * wv.x) * invB;
            o.y = wv.y + (a1 - s * wv.y) * invB;
            *(float2*)&out[idx] = o;
        }
    }

    // emit bmu indices (as float) after the map if there is room
    if (bx < 4 && t < 256 && out_size >= NODES * FEATS + BATCH) {
        int b = bx * 256 + t;
        out[NODES * FEATS + b] =
            (float)(unsigned)(g_best[b] & 0xFFFFFFFFull);
    }
}

// ============================================================
extern "C" void kernel_launch(void* const* d_in, const int* in_sizes, int n_in,
                              void* d_out, int out_size) {
    const float* x = nullptr;
    const float* w = nullptr;
    const int* iter = nullptr;
    for (int i = 0; i < n_in; i++) {
        if (in_sizes[i] == BATCH * FEATS)      x = (const float*)d_in[i];
        else if (in_sizes[i] == NODES * FEATS) w = (const float*)d_in[i];
        else if (in_sizes[i] == 1)             iter = (const int*)d_in[i];
    }
    float* out = (float*)d_out;

    cudaFuncSetAttribute(k_bmu, cudaFuncAttributeMaxDynamicSharedMemorySize, SM_BMU);

    k_prep_all<<<704, 256>>>(x, w, iter);
    dim3 gb(NODES / 256, BATCH / 128);
    k_bmu<<<gb, 512, SM_BMU>>>();
    k_update<<<(NODES / 64) * (FEATS / 128), 512>>>(w, out, out_size);
}

// round 6
// speedup vs baseline: 3.3051x; 1.0752x over previous
#include <cuda_runtime.h>
#include <cuda_fp16.h>
#include <stdint.h>

// ---- SOM constants (match reference) ----
#define NODES 4096
#define FEATS 256
#define BATCH 1024
#define SIGMA_F 70.4f        // max(M,N) * 1.1
#define TOTAL_ITER_F 100000.0f

typedef unsigned long long u64;

// ---- device scratch (no allocations allowed) ----
__device__ u64   g_best[BATCH];
__device__ float g_w2[NODES];
__device__ float g_params[3];   // [0]=lr, [1]=1/(2 r^2), [2]=r^2
__device__ __align__(16) __half g_xh[BATCH * FEATS];
__device__ __align__(16) __half g_xl[BATCH * FEATS];
__device__ __align__(16) __half g_wh[NODES * FEATS];
__device__ __align__(16) __half g_wl[NODES * FEATS];
__device__ __align__(16) __half g_xt[FEATS * BATCH];   // x transposed, fp16

// ---- PTX helpers ----
__device__ __forceinline__ uint32_t smem_u32(const void* p) {
    uint32_t a;
    asm("{ .reg .u64 t; cvta.to.shared.u64 t, %1; cvt.u32.u64 %0, t; }"
        : "=r"(a) : "l"(p));
    return a;
}
__device__ __forceinline__ void cp16(uint32_t dst, const void* src) {
    asm volatile("cp.async.cg.shared.global [%0], [%1], 16;"
                 :: "r"(dst), "l"(src));
}
#define CP_COMMIT() asm volatile("cp.async.commit_group;" ::: "memory")
#define CP_WAIT0()  asm volatile("cp.async.wait_group 0;" ::: "memory")

__device__ __forceinline__ void ldsm4(uint32_t* r, uint32_t addr) {
    asm volatile("ldmatrix.sync.aligned.m8n8.x4.shared.b16 {%0,%1,%2,%3}, [%4];"
                 : "=r"(r[0]), "=r"(r[1]), "=r"(r[2]), "=r"(r[3]) : "r"(addr));
}
__device__ __forceinline__ void mma16816(float* c, const uint32_t* a,
                                         const uint32_t* b) {
    asm volatile(
        "mma.sync.aligned.m16n8k16.row.col.f32.f16.f16.f32 "
        "{%0,%1,%2,%3}, {%4,%5,%6,%7}, {%8,%9}, {%0,%1,%2,%3};"
        : "+f"(c[0]), "+f"(c[1]), "+f"(c[2]), "+f"(c[3])
        : "r"(a[0]), "r"(a[1]), "r"(a[2]), "r"(a[3]), "r"(b[0]), "r"(b[1]));
}
__device__ __forceinline__ u64 packkey(float d, int n) {
    unsigned u = __float_as_uint(d);
    u = (u & 0x80000000u) ? ~u : (u | 0x80000000u);
    return ((u64)u << 32) | (unsigned)n;
}

// ============================================================
// K1: fused prep, vectorized (8 floats / thread / row pass).
// Blocks [0,512): w split+w2; [512,640): x split; [640,704):
// x transpose (+ g_best reset + params in first 4).
// ============================================================
__device__ __forceinline__ void split8(const float* src, __half* hi, __half* lo,
                                       float* sumsq) {
    float4 va = ((const float4*)src)[0];
    float4 vb = ((const float4*)src)[1];
    float f[8] = {va.x, va.y, va.z, va.w, vb.x, vb.y, vb.z, vb.w};
    __half2 h2[4], l2[4];
    float s = 0.0f;
    #pragma unroll
    for (int i = 0; i < 4; i++) {
        float a = f[2 * i], b = f[2 * i + 1];
        s += a * a + b * b;
        float ha = __half2float(__float2half_rn(a));
        float hb = __half2float(__float2half_rn(b));
        h2[i] = __floats2half2_rn(ha, hb);
        l2[i] = __floats2half2_rn(a - ha, b - hb);
    }
    *(uint4*)hi = *(uint4*)h2;
    *(uint4*)lo = *(uint4*)l2;
    if (sumsq) *sumsq = s;
}

__global__ void __launch_bounds__(256) k_prep_all(const float* __restrict__ x,
                                                  const float* __restrict__ w,
                                                  const int* __restrict__ iter) {
    int bid = blockIdx.x;
    int t = threadIdx.x;
    int warp = t >> 5, lane = t & 31;

    if (bid < 512) {                       // w rows: split + w2
        int n = bid * 8 + warp;
        int c = lane * 8;
        float s;
        split8(w + (size_t)n * FEATS + c, g_wh + n * FEATS + c,
               g_wl + n * FEATS + c, &s);
        #pragma unroll
        for (int o = 16; o; o >>= 1) s += __shfl_xor_sync(0xFFFFFFFFu, s, o);
        if (lane == 0) g_w2[n] = s;
    } else if (bid < 640) {                // x rows: split
        int r = (bid - 512) * 8 + warp;
        int c = lane * 8;
        split8(x + (size_t)r * FEATS + c, g_xh + r * FEATS + c,
               g_xl + r * FEATS + c, nullptr);
    } else {                               // x transpose tiles
        __shared__ float s[64][65];
        int bx2 = bid - 640;
        if (bx2 < 4) {
            g_best[bx2 * 256 + t] = 0xFFFFFFFFFFFFFFFFull;
            if (bx2 == 0 && t == 0) {
                float lambda_g = TOTAL_ITER_F / SIGMA_F;
                float decay    = expf(-(float)iter[0] / lambda_g);
                float radius   = SIGMA_F * decay + 1e-6f;
                g_params[0] = 0.5f * decay;
                g_params[1] = 1.0f / (2.0f * radius * radius);
                g_params[2] = radius * radius;
            }
        }
        int b0 = (bx2 >> 2) * 64, d0 = (bx2 & 3) * 64;
        #pragma unroll
        for (int q = 0; q < 16; q++) {
            int e = q * 256 + t;
            int br = e >> 6, dc = e & 63;
            s[br][dc] = x[(size_t)(b0 + br) * FEATS + d0 + dc];
        }
        __syncthreads();
        #pragma unroll
        for (int q = 0; q < 16; q++) {
            int e = q * 256 + t;
            int dr = e >> 6, bc = e & 63;
            g_xt[(size_t)(d0 + dr) * BATCH + b0 + bc] = __float2half_rn(s[bc][dr]);
        }
    }
}

// ============================================================
// K2: BMU GEMM via HMMA. 256 thr, CTA tile 128m x 128n, grid 256
// (2 CTAs/SM for barrier overlap). Warps 4m x 2n (32m x 64n each).
// K = 3 terms x 256 (AhBh + AhBl + AlBh), 12 chunks of 64.
// ============================================================
#define ASZ (128 * 144)
#define BSZ (128 * 144)
#define OFF_A 1024
#define OFF_B (1024 + 2 * ASZ)
#define SM_BMU (OFF_B + 2 * BSZ)

__device__ __forceinline__ void stage_bmu(uint32_t sb, int buf, int ch,
                                          int m0, int n0, int t) {
    int term = ch >> 2;
    int kk = (ch & 3) * 64;
    const __half* asrc = (term < 2) ? g_xh : g_xl;
    const __half* bsrc = (term == 1) ? g_wl : g_wh;
    uint32_t adst = sb + OFF_A + buf * ASZ;
    uint32_t bdst = sb + OFF_B + buf * BSZ;
    #pragma unroll
    for (int q = 0; q < 4; q++) {
        int g = t + 256 * q; int r = g >> 3, c = g & 7;
        cp16(adst + r * 144 + c * 16, asrc + (size_t)(m0 + r) * FEATS + kk + c * 8);
        cp16(bdst + r * 144 + c * 16, bsrc + (size_t)(n0 + r) * FEATS + kk + c * 8);
    }
    CP_COMMIT();
}

__global__ void __launch_bounds__(256, 2) k_bmu() {
    extern __shared__ char sm[];
    uint32_t sb = smem_u32(sm);
    float* w2s = (float*)sm;
    int t = threadIdx.x, lane = t & 31, warp = t >> 5;
    int wm = warp >> 1, wn = warp & 1;     // 4m x 2n warp grid
    int n0 = blockIdx.x * 128;
    int m0 = blockIdx.y * 128;

    if (t < 128) w2s[t] = g_w2[n0 + t];

    float c[2][8][4];
    #pragma unroll
    for (int i = 0; i < 2; i++)
        #pragma unroll
        for (int j = 0; j < 8; j++)
            #pragma unroll
            for (int q = 0; q < 4; q++) c[i][j][q] = 0.0f;

    uint32_t aoff = (uint32_t)((lane & 15) * 144 + (lane >> 4) * 16);
    uint32_t boff = (uint32_t)(((lane & 7) + ((lane >> 4) << 3)) * 144
                               + (((lane >> 3) & 1) << 4));

    stage_bmu(sb, 0, 0, m0, n0, t);
    for (int ch = 0; ch < 12; ch++) {
        CP_WAIT0();
        __syncthreads();
        if (ch + 1 < 12) stage_bmu(sb, (ch + 1) & 1, ch + 1, m0, n0, t);

        uint32_t Ab = sb + OFF_A + (ch & 1) * ASZ + (wm * 32) * 144 + aoff;
        uint32_t Bb = sb + OFF_B + (ch & 1) * BSZ + (wn * 64) * 144 + boff;
        #pragma unroll
        for (int k16 = 0; k16 < 4; k16++) {
            uint32_t a[2][4], b[4][4];
            #pragma unroll
            for (int im = 0; im < 2; im++)
                ldsm4(a[im], Ab + im * 16 * 144 + k16 * 32);
            #pragma unroll
            for (int j2 = 0; j2 < 4; j2++)
                ldsm4(b[j2], Bb + j2 * 16 * 144 + k16 * 32);
            #pragma unroll
            for (int im = 0; im < 2; im++)
                #pragma unroll
                for (int j2 = 0; j2 < 4; j2++) {
                    mma16816(c[im][2 * j2],     a[im], b[j2]);
                    mma16816(c[im][2 * j2 + 1], a[im], b[j2] + 2);
                }
        }
        __syncthreads();
    }

    // fused argmin epilogue
    #pragma unroll
    for (int im = 0; im < 2; im++) {
        #pragma unroll
        for (int h = 0; h < 2; h++) {
            float best = __int_as_float(0x7F800000);
            int bestn = 0;
            #pragma unroll
            for (int j8 = 0; j8 < 8; j8++) {
                int nl = wn * 64 + j8 * 8 + 2 * (lane & 3);
                float v0 = w2s[nl]     - 2.0f * c[im][j8][2 * h];
                float v1 = w2s[nl + 1] - 2.0f * c[im][j8][2 * h + 1];
                if (v0 < best) { best = v0; bestn = nl; }
                if (v1 < best) { best = v1; bestn = nl + 1; }
            }
            #pragma unroll
            for (int o = 1; o <= 2; o <<= 1) {
                float od = __shfl_xor_sync(0xFFFFFFFFu, best, o);
                int   on = __shfl_xor_sync(0xFFFFFFFFu, bestn, o);
                if (od < best || (od == best && on < bestn)) { best = od; bestn = on; }
            }
            if ((lane & 3) == 0) {
                int m = m0 + wm * 32 + im * 16 + h * 8 + (lane >> 2);
                atomicMin(&g_best[m], packkey(best, n0 + bestn));
            }
        }
    }
}

// ============================================================
// K3: update GEMM via HMMA. 256 thr, CTA tile 32n x 128d, grid 256
// (128 n-blocks x 2 d-blocks, 2 CTAs/SM). Warps 2n x 4d (16n x 32d).
// C[n,d] = sum_b L[n,b]*Xt[d,b]; L regenerated per 64-b chunk.
// ============================================================
__global__ void __launch_bounds__(256, 2) k_update(const float* __restrict__ w,
                                                   float* __restrict__ out,
                                                   int out_size) {
    __shared__ float s_sm[32];
    __shared__ float s_part[256];
    __shared__ __align__(16) __half Ls[32 * 72];
    __shared__ __align__(16) __half Xs[2][128 * 72];

    uint32_t sbL = smem_u32(Ls);
    uint32_t sbX = smem_u32(Xs);

    int t = threadIdx.x, lane = t & 31, warp = t >> 5;
    int wn = warp >> 2, wd = warp & 3;     // 2n x 4d warp grid
    int bx = blockIdx.x;
    int n0 = (bx >> 1) * 32;
    int d0 = (bx & 1) * 128;

    float lr = g_params[0], inv2r2 = g_params[1], r2 = g_params[2];

    int n_l = t & 31;
    int gn = n0 + n_l;
    int ni = gn >> 6, nj = gn & 63;
    int bgrp = t >> 5;          // 0..7
    float s_local = 0.0f;

    float c[4][4];
    #pragma unroll
    for (int j = 0; j < 4; j++)
        #pragma unroll
        for (int q = 0; q < 4; q++) c[j][q] = 0.0f;

    uint32_t aoff = (uint32_t)((lane & 15) * 144 + (lane >> 4) * 16);
    uint32_t boff = (uint32_t)(((lane & 7) + ((lane >> 4) << 3)) * 144
                               + (((lane >> 3) & 1) << 4));

    // prefetch X chunk 0 (128 rows x 8 granules = 1024; 4 per thread)
    #pragma unroll
    for (int q = 0; q < 4; q++) {
        int g = t + 256 * q; int r = g >> 3, cc = g & 7;
        cp16(sbX + r * 144 + cc * 16, g_xt + (size_t)(d0 + r) * BATCH + cc * 8);
    }
    CP_COMMIT();

    for (int ch = 0; ch < 16; ch++) {
        int bc0 = ch * 64;
        CP_WAIT0();
        __syncthreads();
        if (ch + 1 < 16) {
            uint32_t xdst = sbX + ((ch + 1) & 1) * (128 * 144);
            #pragma unroll
            for (int q = 0; q < 4; q++) {
                int g = t + 256 * q; int r = g >> 3, cc = g & 7;
                cp16(xdst + r * 144 + cc * 16,
                     g_xt + (size_t)(d0 + r) * BATCH + (ch + 1) * 64 + cc * 8);
            }
            CP_COMMIT();
        }
        // generate L tile [32n][64b]: thread n = t&31, b = bgrp+8j
        #pragma unroll
        for (int j = 0; j < 8; j++) {
            int bb = bgrp + 8 * j;
            int bmu = (int)(unsigned)(g_best[bc0 + bb] & 0xFFFFFFFFull);
            int di = ni - (bmu >> 6);
            int dj = nj - (bmu & 63);
            float d2 = (float)(di * di + dj * dj);
            float v = (d2 <= r2) ? lr * __expf(-d2 * inv2r2) : 0.0f;
            Ls[n_l * 72 + bb] = __float2half_rn(v);
            s_local += v;
        }
        __syncthreads();

        uint32_t Ab = sbL + (wn * 16) * 144 + aoff;
        uint32_t Bb = sbX + (ch & 1) * (128 * 144) + (wd * 32) * 144 + boff;
        #pragma unroll
        for (int k16 = 0; k16 < 4; k16++) {
            uint32_t a[4], b[2][4];
            ldsm4(a, Ab + k16 * 32);
            #pragma unroll
            for (int j2 = 0; j2 < 2; j2++)
                ldsm4(b[j2], Bb + j2 * 16 * 144 + k16 * 32);
            #pragma unroll
            for (int jd = 0; jd < 4; jd++)
                mma16816(c[jd], a, b[jd >> 1] + (jd & 1) * 2);
        }
        __syncthreads();
    }

    // reduce column sums S[n] over the 8 b-groups
    s_part[t] = s_local;
    __syncthreads();
    if (t < 32) {
        float s = 0.0f;
        #pragma unroll
        for (int g = 0; g < 8; g++) s += s_part[t + 32 * g];
        s_sm[t] = s;
    }
    __syncthreads();

    const float invB = 1.0f / (float)BATCH;
    #pragma unroll
    for (int h = 0; h < 2; h++) {
        int nl = wn * 16 + h * 8 + (lane >> 2);
        int n = n0 + nl;
        float s = s_sm[nl];
        #pragma unroll
        for (int jd = 0; jd < 4; jd++) {
            int d = d0 + wd * 32 + jd * 8 + 2 * (lane & 3);
            size_t idx = (size_t)n * FEATS + d;
            float2 wv = *(const float2*)&w[idx];
            float a0 = c[jd][2 * h], a1 = c[jd][2 * h + 1];
            float2 o;
            o.x = wv.x + (a0 - s * wv.x) * invB;
            o.y = wv.y + (a1 - s * wv.y) * invB;
            *(float2*)&out[idx] = o;
        }
    }

    // emit bmu indices (as float) after the map if there is room
    if (bx < 4 && out_size >= NODES * FEATS + BATCH) {
        int b = bx * 256 + t;
        out[NODES * FEATS + b] =
            (float)(unsigned)(g_best[b] & 0xFFFFFFFFull);
    }
}

// ============================================================
extern "C" void kernel_launch(void* const* d_in, const int* in_sizes, int n_in,
                              void* d_out, int out_size) {
    const float* x = nullptr;
    const float* w = nullptr;
    const int* iter = nullptr;
    for (int i = 0; i < n_in; i++) {
        if (in_sizes[i] == BATCH * FEATS)      x = (const float*)d_in[i];
        else if (in_sizes[i] == NODES * FEATS) w = (const float*)d_in[i];
        else if (in_sizes[i] == 1)             iter = (const int*)d_in[i];
    }
    float* out = (float*)d_out;

    cudaFuncSetAttribute(k_bmu, cudaFuncAttributeMaxDynamicSharedMemorySize, SM_BMU);

    k_prep_all<<<704, 256>>>(x, w, iter);
    dim3 gb(NODES / 128, BATCH / 128);
    k_bmu<<<gb, 256, SM_BMU>>>();
    k_update<<<(NODES / 32) * (FEATS / 128), 256>>>(w, out, out_size);
}

// round 7
// speedup vs baseline: 3.3690x; 1.0193x over previous
#include <cuda_runtime.h>
#include <cuda_fp16.h>
#include <stdint.h>

// ---- SOM constants (match reference) ----
#define NODES 4096
#define FEATS 256
#define BATCH 1024
#define SIGMA_F 70.4f        // max(M,N) * 1.1
#define TOTAL_ITER_F 100000.0f

typedef unsigned long long u64;

// ---- device scratch (no allocations allowed) ----
__device__ u64   g_best[BATCH];
__device__ float g_w2[NODES];
__device__ float g_params[3];   // [0]=lr, [1]=1/(2 r^2), [2]=r^2
__device__ __align__(16) __half g_xh[BATCH * FEATS];
__device__ __align__(16) __half g_xl[BATCH * FEATS];
__device__ __align__(16) __half g_wh[NODES * FEATS];
__device__ __align__(16) __half g_wl[NODES * FEATS];
__device__ __align__(16) __half g_xt[FEATS * BATCH];   // x transposed, fp16

// ---- PTX helpers ----
__device__ __forceinline__ uint32_t smem_u32(const void* p) {
    uint32_t a;
    asm("{ .reg .u64 t; cvta.to.shared.u64 t, %1; cvt.u32.u64 %0, t; }"
        : "=r"(a) : "l"(p));
    return a;
}
__device__ __forceinline__ void cp16(uint32_t dst, const void* src) {
    asm volatile("cp.async.cg.shared.global [%0], [%1], 16;"
                 :: "r"(dst), "l"(src));
}
#define CP_COMMIT() asm volatile("cp.async.commit_group;" ::: "memory")
#define CP_WAIT0()  asm volatile("cp.async.wait_group 0;" ::: "memory")

__device__ __forceinline__ void ldsm4(uint32_t* r, uint32_t addr) {
    asm volatile("ldmatrix.sync.aligned.m8n8.x4.shared.b16 {%0,%1,%2,%3}, [%4];"
                 : "=r"(r[0]), "=r"(r[1]), "=r"(r[2]), "=r"(r[3]) : "r"(addr));
}
__device__ __forceinline__ void mma16816(float* c, const uint32_t* a,
                                         const uint32_t* b) {
    asm volatile(
        "mma.sync.aligned.m16n8k16.row.col.f32.f16.f16.f32 "
        "{%0,%1,%2,%3}, {%4,%5,%6,%7}, {%8,%9}, {%0,%1,%2,%3};"
        : "+f"(c[0]), "+f"(c[1]), "+f"(c[2]), "+f"(c[3])
        : "r"(a[0]), "r"(a[1]), "r"(a[2]), "r"(a[3]), "r"(b[0]), "r"(b[1]));
}
__device__ __forceinline__ u64 packkey(float d, int n) {
    unsigned u = __float_as_uint(d);
    u = (u & 0x80000000u) ? ~u : (u | 0x80000000u);
    return ((u64)u << 32) | (unsigned)n;
}

// ============================================================
// K1: fused prep, MLP-deep. Blocks [0,64): w split+w2 (64 rows
// each); [64,80): x split (64 rows each); [80,144): x transpose
// (+ g_best reset + params in first 4 of the transpose range).
// ============================================================
__device__ __forceinline__ void split8(const float* src, __half* hi, __half* lo,
                                       float* sumsq) {
    float4 va = ((const float4*)src)[0];
    float4 vb = ((const float4*)src)[1];
    float f[8] = {va.x, va.y, va.z, va.w, vb.x, vb.y, vb.z, vb.w};
    __half2 h2[4], l2[4];
    float s = 0.0f;
    #pragma unroll
    for (int i = 0; i < 4; i++) {
        float a = f[2 * i], b = f[2 * i + 1];
        s += a * a + b * b;
        float ha = __half2float(__float2half_rn(a));
        float hb = __half2float(__float2half_rn(b));
        h2[i] = __floats2half2_rn(ha, hb);
        l2[i] = __floats2half2_rn(a - ha, b - hb);
    }
    *(uint4*)hi = *(uint4*)h2;
    *(uint4*)lo = *(uint4*)l2;
    if (sumsq) *sumsq = s;
}

__global__ void __launch_bounds__(256) k_prep_all(const float* __restrict__ x,
                                                  const float* __restrict__ w,
                                                  const int* __restrict__ iter) {
    int bid = blockIdx.x;
    int t = threadIdx.x;
    int warp = t >> 5, lane = t & 31;
    int c = lane * 8;

    if (bid < 64) {                        // w rows: split + w2 (8 rows/warp)
        int r0 = bid * 64 + warp * 8;
        #pragma unroll
        for (int i = 0; i < 8; i++) {
            int n = r0 + i;
            float s;
            split8(w + (size_t)n * FEATS + c, g_wh + n * FEATS + c,
                   g_wl + n * FEATS + c, &s);
            #pragma unroll
            for (int o = 16; o; o >>= 1) s += __shfl_xor_sync(0xFFFFFFFFu, s, o);
            if (lane == 0) g_w2[n] = s;
        }
    } else if (bid < 80) {                 // x rows: split (8 rows/warp)
        int r0 = (bid - 64) * 64 + warp * 8;
        #pragma unroll
        for (int i = 0; i < 8; i++) {
            int r = r0 + i;
            split8(x + (size_t)r * FEATS + c, g_xh + r * FEATS + c,
                   g_xl + r * FEATS + c, nullptr);
        }
    } else {                               // x transpose tiles
        __shared__ float s[64][65];
        int bx2 = bid - 80;
        if (bx2 < 4) {
            g_best[bx2 * 256 + t] = 0xFFFFFFFFFFFFFFFFull;
            if (bx2 == 0 && t == 0) {
                float lambda_g = TOTAL_ITER_F / SIGMA_F;
                float decay    = expf(-(float)iter[0] / lambda_g);
                float radius   = SIGMA_F * decay + 1e-6f;
                g_params[0] = 0.5f * decay;
                g_params[1] = 1.0f / (2.0f * radius * radius);
                g_params[2] = radius * radius;
            }
        }
        int b0 = (bx2 >> 2) * 64, d0 = (bx2 & 3) * 64;
        #pragma unroll
        for (int q = 0; q < 16; q++) {
            int e = q * 256 + t;
            int br = e >> 6, dc = e & 63;
            s[br][dc] = x[(size_t)(b0 + br) * FEATS + d0 + dc];
        }
        __syncthreads();
        #pragma unroll
        for (int q = 0; q < 16; q++) {
            int e = q * 256 + t;
            int dr = e >> 6, bc = e & 63;
            g_xt[(size_t)(d0 + dr) * BATCH + b0 + bc] = __float2half_rn(s[bc][dr]);
        }
    }
}

// ============================================================
// K2: BMU GEMM via HMMA. 256 thr, CTA tile 128m x 128n, grid 256
// (2 CTAs/SM). Warps 4m x 2n (32m x 64n each). ONE sync/chunk.
// K = 3 terms x 256 (AhBh + AhBl + AlBh), 12 chunks of 64.
// ============================================================
#define ASZ (128 * 144)
#define BSZ (128 * 144)
#define OFF_A 1024
#define OFF_B (1024 + 2 * ASZ)
#define SM_BMU (OFF_B + 2 * BSZ)

__device__ __forceinline__ void stage_bmu(uint32_t sb, int buf, int ch,
                                          int m0, int n0, int t) {
    int term = ch >> 2;
    int kk = (ch & 3) * 64;
    const __half* asrc = (term < 2) ? g_xh : g_xl;
    const __half* bsrc = (term == 1) ? g_wl : g_wh;
    uint32_t adst = sb + OFF_A + buf * ASZ;
    uint32_t bdst = sb + OFF_B + buf * BSZ;
    #pragma unroll
    for (int q = 0; q < 4; q++) {
        int g = t + 256 * q; int r = g >> 3, c = g & 7;
        cp16(adst + r * 144 + c * 16, asrc + (size_t)(m0 + r) * FEATS + kk + c * 8);
        cp16(bdst + r * 144 + c * 16, bsrc + (size_t)(n0 + r) * FEATS + kk + c * 8);
    }
    CP_COMMIT();
}

__global__ void __launch_bounds__(256, 2) k_bmu() {
    extern __shared__ char sm[];
    uint32_t sb = smem_u32(sm);
    float* w2s = (float*)sm;
    int t = threadIdx.x, lane = t & 31, warp = t >> 5;
    int wm = warp >> 1, wn = warp & 1;     // 4m x 2n warp grid
    int n0 = blockIdx.x * 128;
    int m0 = blockIdx.y * 128;

    if (t < 128) w2s[t] = g_w2[n0 + t];

    float c[2][8][4];
    #pragma unroll
    for (int i = 0; i < 2; i++)
        #pragma unroll
        for (int j = 0; j < 8; j++)
            #pragma unroll
            for (int q = 0; q < 4; q++) c[i][j][q] = 0.0f;

    uint32_t aoff = (uint32_t)((lane & 15) * 144 + (lane >> 4) * 16);
    uint32_t boff = (uint32_t)(((lane & 7) + ((lane >> 4) << 3)) * 144
                               + (((lane >> 3) & 1) << 4));

    stage_bmu(sb, 0, 0, m0, n0, t);
    for (int ch = 0; ch < 12; ch++) {
        CP_WAIT0();
        __syncthreads();   // data visible + prior-iter reads of buf^1 done
        if (ch + 1 < 12) stage_bmu(sb, (ch + 1) & 1, ch + 1, m0, n0, t);

        uint32_t Ab = sb + OFF_A + (ch & 1) * ASZ + (wm * 32) * 144 + aoff;
        uint32_t Bb = sb + OFF_B + (ch & 1) * BSZ + (wn * 64) * 144 + boff;
        #pragma unroll
        for (int k16 = 0; k16 < 4; k16++) {
            uint32_t a[2][4], b[4][4];
            #pragma unroll
            for (int im = 0; im < 2; im++)
                ldsm4(a[im], Ab + im * 16 * 144 + k16 * 32);
            #pragma unroll
            for (int j2 = 0; j2 < 4; j2++)
                ldsm4(b[j2], Bb + j2 * 16 * 144 + k16 * 32);
            #pragma unroll
            for (int im = 0; im < 2; im++)
                #pragma unroll
                for (int j2 = 0; j2 < 4; j2++) {
                    mma16816(c[im][2 * j2],     a[im], b[j2]);
                    mma16816(c[im][2 * j2 + 1], a[im], b[j2] + 2);
                }
        }
    }

    // fused argmin epilogue
    #pragma unroll
    for (int im = 0; im < 2; im++) {
        #pragma unroll
        for (int h = 0; h < 2; h++) {
            float best = __int_as_float(0x7F800000);
            int bestn = 0;
            #pragma unroll
            for (int j8 = 0; j8 < 8; j8++) {
                int nl = wn * 64 + j8 * 8 + 2 * (lane & 3);
                float v0 = w2s[nl]     - 2.0f * c[im][j8][2 * h];
                float v1 = w2s[nl + 1] - 2.0f * c[im][j8][2 * h + 1];
                if (v0 < best) { best = v0; bestn = nl; }
                if (v1 < best) { best = v1; bestn = nl + 1; }
            }
            #pragma unroll
            for (int o = 1; o <= 2; o <<= 1) {
                float od = __shfl_xor_sync(0xFFFFFFFFu, best, o);
                int   on = __shfl_xor_sync(0xFFFFFFFFu, bestn, o);
                if (od < best || (od == best && on < bestn)) { best = od; bestn = on; }
            }
            if ((lane & 3) == 0) {
                int m = m0 + wm * 32 + im * 16 + h * 8 + (lane >> 2);
                atomicMin(&g_best[m], packkey(best, n0 + bestn));
            }
        }
    }
}

// ============================================================
// K3: update GEMM via HMMA. 256 thr, CTA tile 32n x 128d, grid 256
// (2 CTAs/SM). Warps 2n x 4d (16n x 32d). L double-buffered and
// generated one chunk ahead (overlapped with MMA). ONE sync/chunk.
// ============================================================
__global__ void __launch_bounds__(256, 2) k_update(const float* __restrict__ w,
                                                   float* __restrict__ out,
                                                   int out_size) {
    __shared__ float s_sm[32];
    __shared__ float s_part[256];
    __shared__ __align__(16) __half Ls[2][32 * 72];
    __shared__ __align__(16) __half Xs[2][128 * 72];

    uint32_t sbL = smem_u32(Ls);
    uint32_t sbX = smem_u32(Xs);

    int t = threadIdx.x, lane = t & 31, warp = t >> 5;
    int wn = warp >> 2, wd = warp & 3;     // 2n x 4d warp grid
    int bx = blockIdx.x;
    int n0 = (bx >> 1) * 32;
    int d0 = (bx & 1) * 128;

    float lr = g_params[0], inv2r2 = g_params[1], r2 = g_params[2];

    int n_l = t & 31;
    int gn = n0 + n_l;
    int ni = gn >> 6, nj = gn & 63;
    int bgrp = t >> 5;          // 0..7
    float s_local = 0.0f;

    float c[4][4];
    #pragma unroll
    for (int j = 0; j < 4; j++)
        #pragma unroll
        for (int q = 0; q < 4; q++) c[j][q] = 0.0f;

    uint32_t aoff = (uint32_t)((lane & 15) * 144 + (lane >> 4) * 16);
    uint32_t boff = (uint32_t)(((lane & 7) + ((lane >> 4) << 3)) * 144
                               + (((lane >> 3) & 1) << 4));

    // L generator for chunk ch into buffer buf (thread n = t&31, b = bgrp+8j)
    auto gen_L = [&](int ch, int buf) {
        int bc0 = ch * 64;
        #pragma unroll
        for (int j = 0; j < 8; j++) {
            int bb = bgrp + 8 * j;
            int bmu = (int)(unsigned)(g_best[bc0 + bb] & 0xFFFFFFFFull);
            int di = ni - (bmu >> 6);
            int dj = nj - (bmu & 63);
            float d2 = (float)(di * di + dj * dj);
            float v = (d2 <= r2) ? lr * __expf(-d2 * inv2r2) : 0.0f;
            Ls[buf][n_l * 72 + bb] = __float2half_rn(v);
            s_local += v;
        }
    };

    // prologue: stage X(0), generate L(0)
    #pragma unroll
    for (int q = 0; q < 4; q++) {
        int g = t + 256 * q; int r = g >> 3, cc = g & 7;
        cp16(sbX + r * 144 + cc * 16, g_xt + (size_t)(d0 + r) * BATCH + cc * 8);
    }
    CP_COMMIT();
    gen_L(0, 0);

    for (int ch = 0; ch < 16; ch++) {
        CP_WAIT0();
        __syncthreads();   // X(ch)+L(ch) visible; prior reads of buf^1 done
        if (ch + 1 < 16) {
            uint32_t xdst = sbX + ((ch + 1) & 1) * (128 * 144);
            #pragma unroll
            for (int q = 0; q < 4; q++) {
                int g = t + 256 * q; int r = g >> 3, cc = g & 7;
                cp16(xdst + r * 144 + cc * 16,
                     g_xt + (size_t)(d0 + r) * BATCH + (ch + 1) * 64 + cc * 8);
            }
            CP_COMMIT();
            gen_L(ch + 1, (ch + 1) & 1);   // overlapped with compute below
        }

        uint32_t Ab = sbL + (ch & 1) * (32 * 144) + (wn * 16) * 144 + aoff;
        uint32_t Bb = sbX + (ch & 1) * (128 * 144) + (wd * 32) * 144 + boff;
        #pragma unroll
        for (int k16 = 0; k16 < 4; k16++) {
            uint32_t a[4], b[2][4];
            ldsm4(a, Ab + k16 * 32);
            #pragma unroll
            for (int j2 = 0; j2 < 2; j2++)
                ldsm4(b[j2], Bb + j2 * 16 * 144 + k16 * 32);
            #pragma unroll
            for (int jd = 0; jd < 4; jd++)
                mma16816(c[jd], a, b[jd >> 1] + (jd & 1) * 2);
        }
    }

    // reduce column sums S[n] over the 8 b-groups
    s_part[t] = s_local;
    __syncthreads();
    if (t < 32) {
        float s = 0.0f;
        #pragma unroll
        for (int g = 0; g < 8; g++) s += s_part[t + 32 * g];
        s_sm[t] = s;
    }
    __syncthreads();

    const float invB = 1.0f / (float)BATCH;
    #pragma unroll
    for (int h = 0; h < 2; h++) {
        int nl = wn * 16 + h * 8 + (lane >> 2);
        int n = n0 + nl;
        float s = s_sm[nl];
        #pragma unroll
        for (int jd = 0; jd < 4; jd++) {
            int d = d0 + wd * 32 + jd * 8 + 2 * (lane & 3);
            size_t idx = (size_t)n * FEATS + d;
            float2 wv = *(const float2*)&w[idx];
            float a0 = c[jd][2 * h], a1 = c[jd][2 * h + 1];
            float2 o;
            o.x = wv.x + (a0 - s * wv.x) * invB;
            o.y = wv.y + (a1 - s * wv.y) * invB;
            *(float2*)&out[idx] = o;
        }
    }

    // emit bmu indices (as float) after the map if there is room
    if (bx < 4 && out_size >= NODES * FEATS + BATCH) {
        int b = bx * 256 + t;
        out[NODES * FEATS + b] =
            (float)(unsigned)(g_best[b] & 0xFFFFFFFFull);
    }
}

// ============================================================
extern "C" void kernel_launch(void* const* d_in, const int* in_sizes, int n_in,
                              void* d_out, int out_size) {
    const float* x = nullptr;
    const float* w = nullptr;
    const int* iter = nullptr;
    for (int i = 0; i < n_in; i++) {
        if (in_sizes[i] == BATCH * FEATS)      x = (const float*)d_in[i];
        else if (in_sizes[i] == NODES * FEATS) w = (const float*)d_in[i];
        else if (in_sizes[i] == 1)             iter = (const int*)d_in[i];
    }
    float* out = (float*)d_out;

    cudaFuncSetAttribute(k_bmu, cudaFuncAttributeMaxDynamicSharedMemorySize, SM_BMU);

    k_prep_all<<<144, 256>>>(x, w, iter);
    dim3 gb(NODES / 128, BATCH / 128);
    k_bmu<<<gb, 256, SM_BMU>>>();
    k_update<<<(NODES / 32) * (FEATS / 128), 256>>>(w, out, out_size);
}